// round 5
// baseline (speedup 1.0000x reference)
#include <cuda_runtime.h>
#include <cuda_bf16.h>

#define NN 100000
#define NE 1600000
#define D0 256
#define D1 128
#define D2 64

// Scratch (device globals — no allocation allowed in kernel_launch)
__device__ int   g_deg[NN];
__device__ float g_dinv[NN];
__device__ float g_hs1[NN * D1];   // dinv-prescaled layer-1 features
__device__ float g_acc1[NN * D1];  // aggregation accumulator (init = hs1 for self-loop)
__device__ float g_hs2[NN * D2];
__device__ float g_acc2[NN * D2];

__device__ __forceinline__ void red_add_v4(float* p, float4 v) {
    asm volatile("red.global.add.v4.f32 [%0], {%1,%2,%3,%4};"
                 :: "l"(p), "f"(v.x), "f"(v.y), "f"(v.z), "f"(v.w) : "memory");
}

// ---------------- degree / dinv ----------------

__global__ void zero_deg_kernel() {
    int i = blockIdx.x * blockDim.x + threadIdx.x;
    if (i < NN) g_deg[i] = 0;
}

__global__ void count_deg_kernel(const int* __restrict__ ei) {
    int e = blockIdx.x * blockDim.x + threadIdx.x;
    if (e < NE) atomicAdd(&g_deg[__ldg(ei + NE + e)], 1);
}

__global__ void dinv_kernel() {
    int i = blockIdx.x * blockDim.x + threadIdx.x;
    if (i < NN) g_dinv[i] = rsqrtf((float)g_deg[i] + 1.0f);
}

// ---------------- GEMM with dinv row-scale epilogue ----------------
// hs[r] = (X[r] @ W) * dinv[r];  acc[r] = hs[r]  (self-loop term pre-seeded)
template <int K, int N, int KT>
__launch_bounds__(256)
__global__ void gemm_scale_kernel(const float* __restrict__ X,
                                  const float* __restrict__ W,
                                  float* __restrict__ hs,
                                  float* __restrict__ acc) {
    constexpr int NV4 = N / 4;          // float4 per output row
    constexpr int GROUPS = 32 / NV4;    // lane groups per warp
    constexpr int RPW = 4 * GROUPS;     // rows per warp
    constexpr int RPB = 8 * RPW;        // rows per block (8 warps)

    __shared__ float sW[KT * N];
    __shared__ float sX[RPB * KT];

    const int warp = threadIdx.x >> 5;
    const int lane = threadIdx.x & 31;
    const int c4 = lane % NV4;
    const int grp = lane / NV4;
    const int rowLocal = warp * RPW + grp * 4;
    const int rowBase = blockIdx.x * RPB;

    float4 accv[4];
#pragma unroll
    for (int j = 0; j < 4; j++) accv[j] = make_float4(0.f, 0.f, 0.f, 0.f);

    const float4* W4 = (const float4*)W;
    const float4* X4 = (const float4*)X;
    float4* sW4 = (float4*)sW;
    float4* sX4 = (float4*)sX;

    for (int kt = 0; kt < K; kt += KT) {
        // stage W tile [KT x N]
        for (int i = threadIdx.x; i < KT * NV4; i += 256) {
            int k = i / NV4, n4 = i % NV4;
            sW4[i] = W4[(kt + k) * NV4 + n4];
        }
        // stage X tile [RPB x KT]
        for (int i = threadIdx.x; i < RPB * (KT / 4); i += 256) {
            int r = i / (KT / 4), kk = i % (KT / 4);
            int gr = rowBase + r;
            float4 v = make_float4(0.f, 0.f, 0.f, 0.f);
            if (gr < NN) v = X4[gr * (K / 4) + kt / 4 + kk];
            sX4[r * (KT / 4) + kk] = v;
        }
        __syncthreads();

#pragma unroll 4
        for (int k = 0; k < KT; k += 4) {
            float4 w0 = sW4[(k + 0) * NV4 + c4];
            float4 w1 = sW4[(k + 1) * NV4 + c4];
            float4 w2 = sW4[(k + 2) * NV4 + c4];
            float4 w3 = sW4[(k + 3) * NV4 + c4];
#pragma unroll
            for (int j = 0; j < 4; j++) {
                float4 ax = *(const float4*)&sX[(rowLocal + j) * KT + k];
                accv[j].x += w0.x * ax.x; accv[j].y += w0.y * ax.x;
                accv[j].z += w0.z * ax.x; accv[j].w += w0.w * ax.x;
                accv[j].x += w1.x * ax.y; accv[j].y += w1.y * ax.y;
                accv[j].z += w1.z * ax.y; accv[j].w += w1.w * ax.y;
                accv[j].x += w2.x * ax.z; accv[j].y += w2.y * ax.z;
                accv[j].z += w2.z * ax.z; accv[j].w += w2.w * ax.z;
                accv[j].x += w3.x * ax.w; accv[j].y += w3.y * ax.w;
                accv[j].z += w3.z * ax.w; accv[j].w += w3.w * ax.w;
            }
        }
        __syncthreads();
    }

    float4* hs4 = (float4*)hs;
    float4* acc4 = (float4*)acc;
#pragma unroll
    for (int j = 0; j < 4; j++) {
        int r = rowBase + rowLocal + j;
        if (r < NN) {
            float s = g_dinv[r];
            float4 v = make_float4(accv[j].x * s, accv[j].y * s,
                                   accv[j].z * s, accv[j].w * s);
            int idx = r * NV4 + c4;
            hs4[idx] = v;
            acc4[idx] = v;
        }
    }
}

// ---------------- edge scatter-add ----------------

// Layer 1: one warp per edge (128 floats = 32 x float4)
__global__ void scatter_l1_kernel(const int* __restrict__ ei) {
    int t = blockIdx.x * blockDim.x + threadIdx.x;
    int e = t >> 5;
    int lane = t & 31;
    if (e >= NE) return;
    int src = __ldg(ei + e);
    int dst = __ldg(ei + NE + e);
    float4 v = ((const float4*)g_hs1)[src * 32 + lane];
    red_add_v4(g_acc1 + dst * 128 + lane * 4, v);
}

// Layer 2: half-warp per edge (64 floats = 16 x float4)
__global__ void scatter_l2_kernel(const int* __restrict__ ei) {
    int t = blockIdx.x * blockDim.x + threadIdx.x;
    int e = ((t >> 5) << 1) + ((t >> 4) & 1);
    int lane16 = t & 15;
    if (e >= NE) return;
    int src = __ldg(ei + e);
    int dst = __ldg(ei + NE + e);
    float4 v = ((const float4*)g_hs2)[src * 16 + lane16];
    red_add_v4(g_acc2 + dst * 64 + lane16 * 4, v);
}

// ---------------- epilogue: out = relu(dinv[row]*acc + b) ----------------
template <int F4>  // float4 per row
__global__ void epilogue_kernel(const float* __restrict__ acc,
                                const float* __restrict__ bias,
                                float* __restrict__ out) {
    int idx = blockIdx.x * blockDim.x + threadIdx.x;
    if (idx >= NN * F4) return;
    int row = idx / F4;
    int c4 = idx % F4;
    float4 v = ((const float4*)acc)[idx];
    float4 b = ((const float4*)bias)[c4];
    float s = g_dinv[row];
    float4 r;
    r.x = fmaxf(v.x * s + b.x, 0.f);
    r.y = fmaxf(v.y * s + b.y, 0.f);
    r.z = fmaxf(v.z * s + b.z, 0.f);
    r.w = fmaxf(v.w * s + b.w, 0.f);
    ((float4*)out)[idx] = r;
}

extern "C" void kernel_launch(void* const* d_in, const int* in_sizes, int n_in,
                              void* d_out, int out_size) {
    const float* x  = (const float*)d_in[0];
    const int*   ei = (const int*)d_in[1];
    const float* W1 = (const float*)d_in[2];
    const float* b1 = (const float*)d_in[3];
    const float* W2 = (const float*)d_in[4];
    const float* b2 = (const float*)d_in[5];
    float* out = (float*)d_out;

    float *p_hs1, *p_acc1, *p_hs2, *p_acc2;
    cudaGetSymbolAddress((void**)&p_hs1,  g_hs1);
    cudaGetSymbolAddress((void**)&p_acc1, g_acc1);
    cudaGetSymbolAddress((void**)&p_hs2,  g_hs2);
    cudaGetSymbolAddress((void**)&p_acc2, g_acc2);

    // degree + dinv
    zero_deg_kernel<<<(NN + 255) / 256, 256>>>();
    count_deg_kernel<<<(NE + 255) / 256, 256>>>(ei);
    dinv_kernel<<<(NN + 255) / 256, 256>>>();

    // layer 1
    gemm_scale_kernel<D0, D1, 64><<<(NN + 31) / 32, 256>>>(x, W1, p_hs1, p_acc1);
    scatter_l1_kernel<<<(NE * 32 + 255) / 256, 256>>>(ei);
    epilogue_kernel<D1 / 4><<<(NN * (D1 / 4) + 255) / 256, 256>>>(p_acc1, b1, p_acc1);

    // layer 2 (input = relu'd acc1, in place)
    gemm_scale_kernel<D1, D2, 64><<<(NN + 63) / 64, 256>>>(p_acc1, W2, p_hs2, p_acc2);
    scatter_l2_kernel<<<((NE + 1) / 2 * 32 + 255) / 256, 256>>>(ei);
    epilogue_kernel<D2 / 4><<<(NN * (D2 / 4) + 255) / 256, 256>>>(p_acc2, b2, out);
}

// round 6
// speedup vs baseline: 1.4920x; 1.4920x over previous
#include <cuda_runtime.h>
#include <cuda_bf16.h>

#define NN 100000
#define NE 1600000
#define D0 256
#define D1 128
#define D2 64
#define SC_BLK 512
#define SC_NB  ((NN + SC_BLK - 1) / SC_BLK)   // 196

// Scratch (device globals — no allocation allowed in kernel_launch)
__device__ int   g_deg[NN];
__device__ float g_dinv[NN];
__device__ int   g_off[NN];       // CSR row offsets (exclusive scan of deg)
__device__ int   g_cursor[NN];
__device__ int   g_csr[NE];       // CSR src indices grouped by dst
__device__ int   g_blk[256];
__device__ int   g_blkoff[256];
__device__ float g_hs1[NN * D1];  // dinv-prescaled layer-1 features
__device__ float g_h1[NN * D1];   // relu'd layer-1 output (input to GEMM2)
__device__ float g_hs2[NN * D2];

// ---------------- degree / dinv ----------------

__global__ void zero_deg_kernel() {
    int i = blockIdx.x * blockDim.x + threadIdx.x;
    if (i < NN) g_deg[i] = 0;
}

__global__ void count_deg_kernel(const int* __restrict__ ei) {
    int e = blockIdx.x * blockDim.x + threadIdx.x;
    if (e < NE) atomicAdd(&g_deg[__ldg(ei + NE + e)], 1);
}

__global__ void dinv_kernel() {
    int i = blockIdx.x * blockDim.x + threadIdx.x;
    if (i < NN) g_dinv[i] = rsqrtf((float)g_deg[i] + 1.0f);
}

// ---------------- CSR build: scan + fill ----------------

__global__ void scan_partial_kernel() {
    __shared__ int s[SC_BLK];
    int t = threadIdx.x;
    int i = blockIdx.x * SC_BLK + t;
    int v = (i < NN) ? g_deg[i] : 0;
    s[t] = v;
    __syncthreads();
#pragma unroll
    for (int off = 1; off < SC_BLK; off <<= 1) {
        int x = 0;
        if (t >= off) x = s[t - off];
        __syncthreads();
        if (t >= off) s[t] += x;
        __syncthreads();
    }
    if (i < NN) g_off[i] = s[t] - v;           // exclusive
    if (t == SC_BLK - 1) g_blk[blockIdx.x] = s[t];
}

__global__ void scan_blk_kernel() {            // 1 block, 256 threads
    __shared__ int s[256];
    int t = threadIdx.x;
    int v = (t < SC_NB) ? g_blk[t] : 0;
    s[t] = v;
    __syncthreads();
#pragma unroll
    for (int off = 1; off < 256; off <<= 1) {
        int x = 0;
        if (t >= off) x = s[t - off];
        __syncthreads();
        if (t >= off) s[t] += x;
        __syncthreads();
    }
    g_blkoff[t] = s[t] - v;                    // exclusive
}

__global__ void scan_add_zero_kernel() {
    int i = blockIdx.x * SC_BLK + threadIdx.x;
    if (i < NN) {
        g_off[i] += g_blkoff[blockIdx.x];
        g_cursor[i] = 0;
    }
}

__global__ void csr_fill_kernel(const int* __restrict__ ei) {
    int e = blockIdx.x * blockDim.x + threadIdx.x;
    if (e >= NE) return;
    int dst = __ldg(ei + NE + e);
    int p = atomicAdd(&g_cursor[dst], 1);
    g_csr[g_off[dst] + p] = __ldg(ei + e);
}

// ---------------- GEMM with dinv row-scale epilogue ----------------
// hs[r] = (X[r] @ W) * dinv[r]
template <int K, int N, int KT>
__launch_bounds__(256)
__global__ void gemm_scale_kernel(const float* __restrict__ X,
                                  const float* __restrict__ W,
                                  float* __restrict__ hs) {
    constexpr int NV4 = N / 4;
    constexpr int GROUPS = 32 / NV4;
    constexpr int RPW = 4 * GROUPS;
    constexpr int RPB = 8 * RPW;

    __shared__ float sW[KT * N];
    __shared__ float sX[RPB * KT];

    const int warp = threadIdx.x >> 5;
    const int lane = threadIdx.x & 31;
    const int c4 = lane % NV4;
    const int grp = lane / NV4;
    const int rowLocal = warp * RPW + grp * 4;
    const int rowBase = blockIdx.x * RPB;

    float4 accv[4];
#pragma unroll
    for (int j = 0; j < 4; j++) accv[j] = make_float4(0.f, 0.f, 0.f, 0.f);

    const float4* W4 = (const float4*)W;
    const float4* X4 = (const float4*)X;
    float4* sW4 = (float4*)sW;
    float4* sX4 = (float4*)sX;

    for (int kt = 0; kt < K; kt += KT) {
        for (int i = threadIdx.x; i < KT * NV4; i += 256) {
            int k = i / NV4, n4 = i % NV4;
            sW4[i] = W4[(kt + k) * NV4 + n4];
        }
        for (int i = threadIdx.x; i < RPB * (KT / 4); i += 256) {
            int r = i / (KT / 4), kk = i % (KT / 4);
            int gr = rowBase + r;
            float4 v = make_float4(0.f, 0.f, 0.f, 0.f);
            if (gr < NN) v = X4[gr * (K / 4) + kt / 4 + kk];
            sX4[r * (KT / 4) + kk] = v;
        }
        __syncthreads();

#pragma unroll 4
        for (int k = 0; k < KT; k += 4) {
            float4 w0 = sW4[(k + 0) * NV4 + c4];
            float4 w1 = sW4[(k + 1) * NV4 + c4];
            float4 w2 = sW4[(k + 2) * NV4 + c4];
            float4 w3 = sW4[(k + 3) * NV4 + c4];
#pragma unroll
            for (int j = 0; j < 4; j++) {
                float4 ax = *(const float4*)&sX[(rowLocal + j) * KT + k];
                accv[j].x += w0.x * ax.x; accv[j].y += w0.y * ax.x;
                accv[j].z += w0.z * ax.x; accv[j].w += w0.w * ax.x;
                accv[j].x += w1.x * ax.y; accv[j].y += w1.y * ax.y;
                accv[j].z += w1.z * ax.y; accv[j].w += w1.w * ax.y;
                accv[j].x += w2.x * ax.z; accv[j].y += w2.y * ax.z;
                accv[j].z += w2.z * ax.z; accv[j].w += w2.w * ax.z;
                accv[j].x += w3.x * ax.w; accv[j].y += w3.y * ax.w;
                accv[j].z += w3.z * ax.w; accv[j].w += w3.w * ax.w;
            }
        }
        __syncthreads();
    }

    float4* hs4 = (float4*)hs;
#pragma unroll
    for (int j = 0; j < 4; j++) {
        int r = rowBase + rowLocal + j;
        if (r < NN) {
            float s = g_dinv[r];
            hs4[r * NV4 + c4] = make_float4(accv[j].x * s, accv[j].y * s,
                                            accv[j].z * s, accv[j].w * s);
        }
    }
}

// ---------------- CSR gather-aggregate + fused epilogue ----------------

// Layer 1: one warp per dst row (128 floats = 32 float4), 8 rows per block.
__launch_bounds__(256)
__global__ void agg1_kernel(const float* __restrict__ bias) {
    int w = threadIdx.x >> 5, lane = threadIdx.x & 31;
    int r = blockIdx.x * 8 + w;
    if (r >= NN) return;
    const float4* hs4 = (const float4*)g_hs1;
    float4 a0 = hs4[r * 32 + lane];    // self-loop term (pre-scaled hs[r])
    float4 a1 = make_float4(0.f, 0.f, 0.f, 0.f);
    int beg = g_off[r], end = beg + g_deg[r];
    int i = beg;
    for (; i + 1 < end; i += 2) {
        int s0 = __ldg(&g_csr[i]);
        int s1 = __ldg(&g_csr[i + 1]);
        float4 v0 = hs4[s0 * 32 + lane];
        float4 v1 = hs4[s1 * 32 + lane];
        a0.x += v0.x; a0.y += v0.y; a0.z += v0.z; a0.w += v0.w;
        a1.x += v1.x; a1.y += v1.y; a1.z += v1.z; a1.w += v1.w;
    }
    if (i < end) {
        int s0 = __ldg(&g_csr[i]);
        float4 v0 = hs4[s0 * 32 + lane];
        a0.x += v0.x; a0.y += v0.y; a0.z += v0.z; a0.w += v0.w;
    }
    a0.x += a1.x; a0.y += a1.y; a0.z += a1.z; a0.w += a1.w;
    float dv = g_dinv[r];
    float4 bb = ((const float4*)bias)[lane];
    float4 o;
    o.x = fmaxf(a0.x * dv + bb.x, 0.f);
    o.y = fmaxf(a0.y * dv + bb.y, 0.f);
    o.z = fmaxf(a0.z * dv + bb.z, 0.f);
    o.w = fmaxf(a0.w * dv + bb.w, 0.f);
    ((float4*)g_h1)[r * 32 + lane] = o;
}

// Layer 2: half-warp per dst row (64 floats = 16 float4), 16 rows per block.
__launch_bounds__(256)
__global__ void agg2_kernel(const float* __restrict__ bias,
                            float* __restrict__ out) {
    int w = threadIdx.x >> 5, lane = threadIdx.x & 31;
    int r = blockIdx.x * 16 + w * 2 + (lane >> 4);
    int l16 = lane & 15;
    if (r >= NN) return;
    const float4* hs4 = (const float4*)g_hs2;
    float4 a0 = hs4[r * 16 + l16];
    float4 a1 = make_float4(0.f, 0.f, 0.f, 0.f);
    int beg = g_off[r], end = beg + g_deg[r];
    int i = beg;
    for (; i + 1 < end; i += 2) {
        int s0 = __ldg(&g_csr[i]);
        int s1 = __ldg(&g_csr[i + 1]);
        float4 v0 = hs4[s0 * 16 + l16];
        float4 v1 = hs4[s1 * 16 + l16];
        a0.x += v0.x; a0.y += v0.y; a0.z += v0.z; a0.w += v0.w;
        a1.x += v1.x; a1.y += v1.y; a1.z += v1.z; a1.w += v1.w;
    }
    if (i < end) {
        int s0 = __ldg(&g_csr[i]);
        float4 v0 = hs4[s0 * 16 + l16];
        a0.x += v0.x; a0.y += v0.y; a0.z += v0.z; a0.w += v0.w;
    }
    a0.x += a1.x; a0.y += a1.y; a0.z += a1.z; a0.w += a1.w;
    float dv = g_dinv[r];
    float4 bb = ((const float4*)bias)[l16];
    float4 o;
    o.x = fmaxf(a0.x * dv + bb.x, 0.f);
    o.y = fmaxf(a0.y * dv + bb.y, 0.f);
    o.z = fmaxf(a0.z * dv + bb.z, 0.f);
    o.w = fmaxf(a0.w * dv + bb.w, 0.f);
    ((float4*)out)[r * 16 + l16] = o;
}

extern "C" void kernel_launch(void* const* d_in, const int* in_sizes, int n_in,
                              void* d_out, int out_size) {
    const float* x  = (const float*)d_in[0];
    const int*   ei = (const int*)d_in[1];
    const float* W1 = (const float*)d_in[2];
    const float* b1 = (const float*)d_in[3];
    const float* W2 = (const float*)d_in[4];
    const float* b2 = (const float*)d_in[5];
    float* out = (float*)d_out;

    float *p_hs1, *p_h1, *p_hs2;
    cudaGetSymbolAddress((void**)&p_hs1, g_hs1);
    cudaGetSymbolAddress((void**)&p_h1,  g_h1);
    cudaGetSymbolAddress((void**)&p_hs2, g_hs2);

    // degree + dinv
    zero_deg_kernel<<<(NN + 255) / 256, 256>>>();
    count_deg_kernel<<<(NE + 255) / 256, 256>>>(ei);
    dinv_kernel<<<(NN + 255) / 256, 256>>>();

    // CSR build
    scan_partial_kernel<<<SC_NB, SC_BLK>>>();
    scan_blk_kernel<<<1, 256>>>();
    scan_add_zero_kernel<<<SC_NB, SC_BLK>>>();
    csr_fill_kernel<<<(NE + 255) / 256, 256>>>(ei);

    // layer 1
    gemm_scale_kernel<D0, D1, 64><<<(NN + 31) / 32, 256>>>(x, W1, p_hs1);
    agg1_kernel<<<(NN + 7) / 8, 256>>>(b1);

    // layer 2
    gemm_scale_kernel<D1, D2, 64><<<(NN + 63) / 64, 256>>>(p_h1, W2, p_hs2);
    agg2_kernel<<<(NN + 15) / 16, 256>>>(b2, out);
}

// round 7
// speedup vs baseline: 1.5681x; 1.0510x over previous
#include <cuda_runtime.h>
#include <cuda_bf16.h>

#define NN 100000
#define NE 1600000
#define D0 256
#define D1 128
#define D2 64
#define SC_BLK 512
#define SC_NB  ((NN + SC_BLK - 1) / SC_BLK)   // 196

// Scratch (device globals — no allocation allowed in kernel_launch)
__device__ int   g_deg[NN];
__device__ float g_dinv[NN];
__device__ int   g_off[NN];       // CSR row offsets (exclusive scan of deg)
__device__ int   g_cursor[NN];
__device__ int   g_csr[NE];       // CSR src indices grouped by dst
__device__ int   g_blk[256];
__device__ int   g_blkoff[256];
__device__ float g_hs1[NN * D1];  // dinv-prescaled layer-1 features
__device__ float g_h1[NN * D1];   // relu'd layer-1 output (input to GEMM2)
__device__ float g_hs2[NN * D2];

// ---------------- f32x2 packed helpers ----------------

__device__ __forceinline__ void fma2(unsigned long long& d,
                                     unsigned long long a,
                                     unsigned long long b) {
    asm("fma.rn.f32x2 %0, %1, %2, %0;" : "+l"(d) : "l"(a), "l"(b));
}

__device__ __forceinline__ unsigned long long dup2(float x) {
    unsigned long long r;
    asm("mov.b64 %0, {%1, %1};" : "=l"(r) : "r"(__float_as_uint(x)));
    return r;
}

__device__ __forceinline__ void mul2(unsigned long long& d,
                                     unsigned long long a,
                                     unsigned long long b) {
    asm("mul.rn.f32x2 %0, %1, %2;" : "=l"(d) : "l"(a), "l"(b));
}

__device__ __forceinline__ void unpack2(unsigned long long v, float& lo, float& hi) {
    unsigned int l, h;
    asm("mov.b64 {%0, %1}, %2;" : "=r"(l), "=r"(h) : "l"(v));
    lo = __uint_as_float(l);
    hi = __uint_as_float(h);
}

// ---------------- degree / dinv ----------------

__global__ void zero_deg_kernel() {
    int i = blockIdx.x * blockDim.x + threadIdx.x;
    if (i < NN) g_deg[i] = 0;
}

__global__ void count_deg_kernel(const int* __restrict__ ei) {
    int e = blockIdx.x * blockDim.x + threadIdx.x;
    if (e < NE) atomicAdd(&g_deg[__ldg(ei + NE + e)], 1);
}

__global__ void dinv_kernel() {
    int i = blockIdx.x * blockDim.x + threadIdx.x;
    if (i < NN) g_dinv[i] = rsqrtf((float)g_deg[i] + 1.0f);
}

// ---------------- CSR build: scan + fill ----------------

__global__ void scan_partial_kernel() {
    __shared__ int s[SC_BLK];
    int t = threadIdx.x;
    int i = blockIdx.x * SC_BLK + t;
    int v = (i < NN) ? g_deg[i] : 0;
    s[t] = v;
    __syncthreads();
#pragma unroll
    for (int off = 1; off < SC_BLK; off <<= 1) {
        int x = 0;
        if (t >= off) x = s[t - off];
        __syncthreads();
        if (t >= off) s[t] += x;
        __syncthreads();
    }
    if (i < NN) g_off[i] = s[t] - v;           // exclusive
    if (t == SC_BLK - 1) g_blk[blockIdx.x] = s[t];
}

__global__ void scan_blk_kernel() {            // 1 block, 256 threads
    __shared__ int s[256];
    int t = threadIdx.x;
    int v = (t < SC_NB) ? g_blk[t] : 0;
    s[t] = v;
    __syncthreads();
#pragma unroll
    for (int off = 1; off < 256; off <<= 1) {
        int x = 0;
        if (t >= off) x = s[t - off];
        __syncthreads();
        if (t >= off) s[t] += x;
        __syncthreads();
    }
    g_blkoff[t] = s[t] - v;                    // exclusive
}

__global__ void scan_add_zero_kernel() {
    int i = blockIdx.x * SC_BLK + threadIdx.x;
    if (i < NN) {
        g_off[i] += g_blkoff[blockIdx.x];
        g_cursor[i] = 0;
    }
}

__global__ void csr_fill_kernel(const int* __restrict__ ei) {
    int e = blockIdx.x * blockDim.x + threadIdx.x;
    if (e >= NE) return;
    int dst = __ldg(ei + NE + e);
    int p = atomicAdd(&g_cursor[dst], 1);
    g_csr[g_off[dst] + p] = __ldg(ei + e);
}

// ---------------- GEMM (f32x2 packed, 8x8 register tile) ----------------
// hs[r] = (X[r] @ W) * dinv[r]
// BM=128 rows/block, full N per block. TM=8 x TN=8 outputs/thread.
// THREADS = (BN/8) * (128/8) = (BN/8)*16.
template <int K, int BN>
__launch_bounds__((BN / 8) * 16)
__global__ void gemm_f32x2_kernel(const float* __restrict__ X,
                                  const float* __restrict__ W,
                                  float* __restrict__ hs) {
    constexpr int BM = 128;
    constexpr int KT = 16;
    constexpr int TX = BN / 8;        // col groups
    constexpr int THREADS = TX * 16;
    constexpr int SXS = BM + 4;       // padded stride (528B, keeps 16B align)

    __shared__ float sX[KT * SXS];    // [k][r] transposed X tile
    __shared__ float sW[KT * BN];     // [k][n]

    const int tid = threadIdx.x;
    const int tx = tid % TX;
    const int ty = tid / TX;
    const int rowBase = blockIdx.x * BM;

    unsigned long long acc[8][4];
#pragma unroll
    for (int m = 0; m < 8; m++)
#pragma unroll
        for (int n = 0; n < 4; n++) acc[m][n] = 0ull;

    const float4* X4 = (const float4*)X;
    const float4* W4 = (const float4*)W;
    float4* sW4 = (float4*)sW;

    for (int kt = 0; kt < K; kt += KT) {
        // stage X tile transposed: sX[k][r]
#pragma unroll
        for (int i = tid; i < BM * (KT / 4); i += THREADS) {
            int row = i >> 2;             // 0..127
            int kq = i & 3;               // which float4 along K
            int gr = rowBase + row;
            float4 v = make_float4(0.f, 0.f, 0.f, 0.f);
            if (gr < NN) v = X4[gr * (K / 4) + (kt >> 2) + kq];
            sX[(kq * 4 + 0) * SXS + row] = v.x;
            sX[(kq * 4 + 1) * SXS + row] = v.y;
            sX[(kq * 4 + 2) * SXS + row] = v.z;
            sX[(kq * 4 + 3) * SXS + row] = v.w;
        }
        // stage W tile row-major: sW[k][n]
#pragma unroll
        for (int i = tid; i < KT * (BN / 4); i += THREADS) {
            int k = i / (BN / 4), n4 = i % (BN / 4);
            sW4[i] = W4[(kt + k) * (BN / 4) + n4];
        }
        __syncthreads();

#pragma unroll
        for (int k = 0; k < KT; k++) {
            // B fragment: 8 cols = 4 f32x2 pairs, loaded as two 16B vectors
            ulonglong2 b01 = *(const ulonglong2*)&sW[k * BN + tx * 8];
            ulonglong2 b23 = *(const ulonglong2*)&sW[k * BN + tx * 8 + 4];
            // A fragment: 8 row scalars
            float4 a03 = *(const float4*)&sX[k * SXS + ty * 8];
            float4 a47 = *(const float4*)&sX[k * SXS + ty * 8 + 4];
            float a[8] = {a03.x, a03.y, a03.z, a03.w, a47.x, a47.y, a47.z, a47.w};
#pragma unroll
            for (int m = 0; m < 8; m++) {
                unsigned long long ap = dup2(a[m]);
                fma2(acc[m][0], ap, b01.x);
                fma2(acc[m][1], ap, b01.y);
                fma2(acc[m][2], ap, b23.x);
                fma2(acc[m][3], ap, b23.y);
            }
        }
        __syncthreads();
    }

    // epilogue: scale rows by dinv, store
#pragma unroll
    for (int m = 0; m < 8; m++) {
        int r = rowBase + ty * 8 + m;
        if (r < NN) {
            unsigned long long dd = dup2(g_dinv[r]);
            float o[8];
#pragma unroll
            for (int n = 0; n < 4; n++) {
                unsigned long long v;
                mul2(v, acc[m][n], dd);
                unpack2(v, o[2 * n], o[2 * n + 1]);
            }
            float4* dst = (float4*)&hs[r * BN + tx * 8];
            dst[0] = make_float4(o[0], o[1], o[2], o[3]);
            dst[1] = make_float4(o[4], o[5], o[6], o[7]);
        }
    }
}

// ---------------- CSR gather-aggregate + fused epilogue ----------------

// Layer 1: one warp per dst row (128 floats = 32 float4), 8 rows per block.
__launch_bounds__(256)
__global__ void agg1_kernel(const float* __restrict__ bias) {
    int w = threadIdx.x >> 5, lane = threadIdx.x & 31;
    int r = blockIdx.x * 8 + w;
    if (r >= NN) return;
    const float4* hs4 = (const float4*)g_hs1;
    float4 a0 = hs4[r * 32 + lane];    // self-loop term (pre-scaled hs[r])
    float4 a1 = make_float4(0.f, 0.f, 0.f, 0.f);
    int beg = g_off[r], end = beg + g_deg[r];
    int i = beg;
    for (; i + 1 < end; i += 2) {
        int s0 = __ldg(&g_csr[i]);
        int s1 = __ldg(&g_csr[i + 1]);
        float4 v0 = hs4[s0 * 32 + lane];
        float4 v1 = hs4[s1 * 32 + lane];
        a0.x += v0.x; a0.y += v0.y; a0.z += v0.z; a0.w += v0.w;
        a1.x += v1.x; a1.y += v1.y; a1.z += v1.z; a1.w += v1.w;
    }
    if (i < end) {
        int s0 = __ldg(&g_csr[i]);
        float4 v0 = hs4[s0 * 32 + lane];
        a0.x += v0.x; a0.y += v0.y; a0.z += v0.z; a0.w += v0.w;
    }
    a0.x += a1.x; a0.y += a1.y; a0.z += a1.z; a0.w += a1.w;
    float dv = g_dinv[r];
    float4 bb = ((const float4*)bias)[lane];
    float4 o;
    o.x = fmaxf(a0.x * dv + bb.x, 0.f);
    o.y = fmaxf(a0.y * dv + bb.y, 0.f);
    o.z = fmaxf(a0.z * dv + bb.z, 0.f);
    o.w = fmaxf(a0.w * dv + bb.w, 0.f);
    ((float4*)g_h1)[r * 32 + lane] = o;
}

// Layer 2: half-warp per dst row (64 floats = 16 float4), 16 rows per block.
__launch_bounds__(256)
__global__ void agg2_kernel(const float* __restrict__ bias,
                            float* __restrict__ out) {
    int w = threadIdx.x >> 5, lane = threadIdx.x & 31;
    int r = blockIdx.x * 16 + w * 2 + (lane >> 4);
    int l16 = lane & 15;
    if (r >= NN) return;
    const float4* hs4 = (const float4*)g_hs2;
    float4 a0 = hs4[r * 16 + l16];
    float4 a1 = make_float4(0.f, 0.f, 0.f, 0.f);
    int beg = g_off[r], end = beg + g_deg[r];
    int i = beg;
    for (; i + 1 < end; i += 2) {
        int s0 = __ldg(&g_csr[i]);
        int s1 = __ldg(&g_csr[i + 1]);
        float4 v0 = hs4[s0 * 16 + l16];
        float4 v1 = hs4[s1 * 16 + l16];
        a0.x += v0.x; a0.y += v0.y; a0.z += v0.z; a0.w += v0.w;
        a1.x += v1.x; a1.y += v1.y; a1.z += v1.z; a1.w += v1.w;
    }
    if (i < end) {
        int s0 = __ldg(&g_csr[i]);
        float4 v0 = hs4[s0 * 16 + l16];
        a0.x += v0.x; a0.y += v0.y; a0.z += v0.z; a0.w += v0.w;
    }
    a0.x += a1.x; a0.y += a1.y; a0.z += a1.z; a0.w += a1.w;
    float dv = g_dinv[r];
    float4 bb = ((const float4*)bias)[l16];
    float4 o;
    o.x = fmaxf(a0.x * dv + bb.x, 0.f);
    o.y = fmaxf(a0.y * dv + bb.y, 0.f);
    o.z = fmaxf(a0.z * dv + bb.z, 0.f);
    o.w = fmaxf(a0.w * dv + bb.w, 0.f);
    ((float4*)out)[r * 16 + l16] = o;
}

extern "C" void kernel_launch(void* const* d_in, const int* in_sizes, int n_in,
                              void* d_out, int out_size) {
    const float* x  = (const float*)d_in[0];
    const int*   ei = (const int*)d_in[1];
    const float* W1 = (const float*)d_in[2];
    const float* b1 = (const float*)d_in[3];
    const float* W2 = (const float*)d_in[4];
    const float* b2 = (const float*)d_in[5];
    float* out = (float*)d_out;

    float *p_hs1, *p_h1, *p_hs2;
    cudaGetSymbolAddress((void**)&p_hs1, g_hs1);
    cudaGetSymbolAddress((void**)&p_h1,  g_h1);
    cudaGetSymbolAddress((void**)&p_hs2, g_hs2);

    // degree + dinv
    zero_deg_kernel<<<(NN + 255) / 256, 256>>>();
    count_deg_kernel<<<(NE + 255) / 256, 256>>>(ei);
    dinv_kernel<<<(NN + 255) / 256, 256>>>();

    // CSR build
    scan_partial_kernel<<<SC_NB, SC_BLK>>>();
    scan_blk_kernel<<<1, 256>>>();
    scan_add_zero_kernel<<<SC_NB, SC_BLK>>>();
    csr_fill_kernel<<<(NE + 255) / 256, 256>>>(ei);

    // layer 1: GEMM (256 threads/block) + gather-aggregate
    gemm_f32x2_kernel<D0, D1><<<(NN + 127) / 128, 256>>>(x, W1, p_hs1);
    agg1_kernel<<<(NN + 7) / 8, 256>>>(b1);

    // layer 2: GEMM (128 threads/block) + gather-aggregate
    gemm_f32x2_kernel<D1, D2><<<(NN + 127) / 128, 128>>>(p_h1, W2, p_hs2);
    agg2_kernel<<<(NN + 15) / 16, 256>>>(b2, out);
}

// round 16
// speedup vs baseline: 1.9970x; 1.2735x over previous
#include <cuda_runtime.h>
#include <cuda_bf16.h>
#include <cstdint>

#define NN 100000
#define NE 1600000
#define D0 256
#define D1 128
#define D2 64
#define SC_BLK 512
#define SC_NB  ((NN + SC_BLK - 1) / SC_BLK)   // 196

// Scratch (device globals — no allocation allowed in kernel_launch)
__device__ int   g_deg[NN];
__device__ float g_dinv[NN];
__device__ int   g_off[NN];
__device__ int   g_cursor[NN];
__device__ int   g_csr[NE];
__device__ int   g_blk[256];
__device__ int   g_blkoff[256];
__device__ float g_hs1[NN * D1];
__device__ float g_h1[NN * D1];
__device__ float g_hs2[NN * D2];
// pre-transposed, hi/lo-split weights: w1t[n][k] = W1[k][n]
__device__ __nv_bfloat16 g_w1t_hi[D1 * D0];
__device__ __nv_bfloat16 g_w1t_lo[D1 * D0];
__device__ __nv_bfloat16 g_w2t_hi[D2 * D1];
__device__ __nv_bfloat16 g_w2t_lo[D2 * D1];

// ---------------- PTX helpers (baseline sm_103-safe ISA only) ----------------

__device__ __forceinline__ uint32_t smem_u32(const void* p) {
    uint32_t a;
    asm("{ .reg .u64 t; cvta.to.shared.u64 t, %1; cvt.u32.u64 %0, t; }"
        : "=r"(a) : "l"(p));
    return a;
}

__device__ __forceinline__ void ldsm_x4(uint32_t* r, uint32_t addr) {
    asm volatile("ldmatrix.sync.aligned.m8n8.x4.shared.b16 {%0,%1,%2,%3}, [%4];"
                 : "=r"(r[0]), "=r"(r[1]), "=r"(r[2]), "=r"(r[3]) : "r"(addr));
}
__device__ __forceinline__ void mma16816(float* c, const uint32_t* a,
                                         uint32_t b0, uint32_t b1) {
    asm volatile(
        "mma.sync.aligned.m16n8k16.row.col.f32.bf16.bf16.f32 "
        "{%0,%1,%2,%3}, {%4,%5,%6,%7}, {%8,%9}, {%0,%1,%2,%3};"
        : "+f"(c[0]), "+f"(c[1]), "+f"(c[2]), "+f"(c[3])
        : "r"(a[0]), "r"(a[1]), "r"(a[2]), "r"(a[3]), "r"(b0), "r"(b1));
}

// ---------------- degree / dinv ----------------

__global__ void zero_deg_kernel() {
    int i = blockIdx.x * blockDim.x + threadIdx.x;
    if (i < NN) g_deg[i] = 0;
}

__global__ void count_deg_kernel(const int* __restrict__ ei) {
    int e = blockIdx.x * blockDim.x + threadIdx.x;
    if (e < NE) atomicAdd(&g_deg[__ldg(ei + NE + e)], 1);
}

__global__ void dinv_kernel() {
    int i = blockIdx.x * blockDim.x + threadIdx.x;
    if (i < NN) g_dinv[i] = rsqrtf((float)g_deg[i] + 1.0f);
}

// ---------------- weight transpose + hi/lo split ----------------

template <int KK, int NO>
__global__ void conv_w_kernel(const float* __restrict__ W,
                              __nv_bfloat16* __restrict__ hi,
                              __nv_bfloat16* __restrict__ lo) {
    int idx = blockIdx.x * blockDim.x + threadIdx.x;
    if (idx >= KK * NO) return;
    int n = idx / KK, k = idx % KK;
    float v = __ldg(&W[k * NO + n]);
    __nv_bfloat16 h = __float2bfloat16(v);
    float r = v - __bfloat162float(h);
    hi[idx] = h;
    lo[idx] = __float2bfloat16(r);
}

// ---------------- CSR build: scan + fill ----------------

__global__ void scan_partial_kernel() {
    __shared__ int s[SC_BLK];
    int t = threadIdx.x;
    int i = blockIdx.x * SC_BLK + t;
    int v = (i < NN) ? g_deg[i] : 0;
    s[t] = v;
    __syncthreads();
#pragma unroll
    for (int off = 1; off < SC_BLK; off <<= 1) {
        int x = 0;
        if (t >= off) x = s[t - off];
        __syncthreads();
        if (t >= off) s[t] += x;
        __syncthreads();
    }
    if (i < NN) g_off[i] = s[t] - v;
    if (t == SC_BLK - 1) g_blk[blockIdx.x] = s[t];
}

__global__ void scan_blk_kernel() {
    __shared__ int s[256];
    int t = threadIdx.x;
    int v = (t < SC_NB) ? g_blk[t] : 0;
    s[t] = v;
    __syncthreads();
#pragma unroll
    for (int off = 1; off < 256; off <<= 1) {
        int x = 0;
        if (t >= off) x = s[t - off];
        __syncthreads();
        if (t >= off) s[t] += x;
        __syncthreads();
    }
    g_blkoff[t] = s[t] - v;
}

__global__ void scan_add_zero_kernel() {
    int i = blockIdx.x * SC_BLK + threadIdx.x;
    if (i < NN) {
        g_off[i] += g_blkoff[blockIdx.x];
        g_cursor[i] = 0;
    }
}

__global__ void csr_fill_kernel(const int* __restrict__ ei) {
    int e = blockIdx.x * blockDim.x + threadIdx.x;
    if (e >= NE) return;
    int dst = __ldg(ei + NE + e);
    int p = atomicAdd(&g_cursor[dst], 1);
    g_csr[g_off[dst] + p] = __ldg(ei + e);
}

// ---------------- HMMA bf16 3-term GEMM (mma.sync, sm_103-safe) ----------------
// hs[r] = (X[r] @ W) * dinv[r]; X fp32 [NN,K], W^T pre-split bf16 [BN,K].
// CTA: 128 rows x BN cols, 8 warps as 4(M) x 2(N). Warp tile 32 x BN/2.
// 3-term split: hi*hi + hi*lo + lo*hi, error ~2^-16 relative.
// B stored [n][k] == col-major B => NON-trans ldmatrix gives the b-fragment.

template <int K, int BN>
__global__ void __launch_bounds__(256)
gemm_mma_kernel(const float* __restrict__ X,
                const __nv_bfloat16* __restrict__ Wt_hi,
                const __nv_bfloat16* __restrict__ Wt_lo,
                float* __restrict__ hs) {
    constexpr int BM = 128, BK = 64;
    constexpr int AS = BK + 8;            // padded stride in bf16 units (144 B)
    constexpr int NT = BN / 16;           // n8-tiles per warp
    constexpr int NG = NT / 2;            // ldmatrix x4 groups per warp
    constexpr int A_HI_B = 0;
    constexpr int A_LO_B = BM * AS * 2;
    constexpr int B_HI_B = 2 * BM * AS * 2;
    constexpr int B_LO_B = B_HI_B + BN * AS * 2;

    extern __shared__ __align__(16) char smem[];
    const uint32_t sb = smem_u32(smem);
    const int tid = threadIdx.x;
    const int wid = tid >> 5, lane = tid & 31;
    const int wm = wid & 3, wn = wid >> 2;
    const int rowBase = blockIdx.x * BM;

    float acc[2][NT][4];
#pragma unroll
    for (int mt = 0; mt < 2; mt++)
#pragma unroll
        for (int nt = 0; nt < NT; nt++)
#pragma unroll
            for (int j = 0; j < 4; j++) acc[mt][nt][j] = 0.f;

    const float4* X4 = (const float4*)X;
    const uint32_t* Bh32 = (const uint32_t*)Wt_hi;   // [BN][K/2] u32
    const uint32_t* Bl32 = (const uint32_t*)Wt_lo;

    // ldmatrix lane addressing (non-trans for both A and B)
    const int a_row = (lane & 7) + ((lane >> 3) & 1) * 8;   // mat 0,2: m0-7; 1,3: m8-15
    const int a_k   = ((lane >> 4) & 1) * 8;                // mat 2,3: k+8
    const int b_n   = (lane & 7) + ((lane >> 4) & 1) * 8;   // mat 2,3: n+8
    const int b_k   = ((lane >> 3) & 1) * 8;                // mat 1,3: k+8

    for (int kt = 0; kt < K; kt += BK) {
        // --- stage A: fp32 -> bf16 hi/lo, [BM x BK] padded rows ---
#pragma unroll 2
        for (int i = tid; i < BM * (BK / 4); i += 256) {
            int row = i >> 4, kq = i & 15;
            int gr = rowBase + row;
            float4 v = make_float4(0.f, 0.f, 0.f, 0.f);
            if (gr < NN) v = __ldg(&X4[gr * (K / 4) + (kt >> 2) + kq]);
            __nv_bfloat162 h01 = __float22bfloat162_rn(make_float2(v.x, v.y));
            __nv_bfloat162 h23 = __float22bfloat162_rn(make_float2(v.z, v.w));
            __nv_bfloat162 l01 = __float22bfloat162_rn(make_float2(
                v.x - __bfloat162float(h01.x), v.y - __bfloat162float(h01.y)));
            __nv_bfloat162 l23 = __float22bfloat162_rn(make_float2(
                v.z - __bfloat162float(h23.x), v.w - __bfloat162float(h23.y)));
            int ob = row * (AS * 2) + kq * 8;   // byte offset, 8B aligned
            *(uint32_t*)(smem + A_HI_B + ob)     = *(uint32_t*)&h01;
            *(uint32_t*)(smem + A_HI_B + ob + 4) = *(uint32_t*)&h23;
            *(uint32_t*)(smem + A_LO_B + ob)     = *(uint32_t*)&l01;
            *(uint32_t*)(smem + A_LO_B + ob + 4) = *(uint32_t*)&l23;
        }
        // --- stage B: copy pre-split bf16, [BN x BK] padded rows ---
#pragma unroll 2
        for (int i = tid; i < BN * (BK / 2); i += 256) {
            int row = i >> 5, q = i & 31;
            int src = row * (K / 2) + (kt >> 1) + q;
            int ob = row * (AS * 2) + q * 4;
            *(uint32_t*)(smem + B_HI_B + ob) = __ldg(&Bh32[src]);
            *(uint32_t*)(smem + B_LO_B + ob) = __ldg(&Bl32[src]);
        }
        __syncthreads();

#pragma unroll
        for (int kk = 0; kk < BK / 16; kk++) {
            uint32_t ah[2][4], al[2][4];
#pragma unroll
            for (int mt = 0; mt < 2; mt++) {
                int row = wm * 32 + mt * 16 + a_row;
                uint32_t ad = sb + A_HI_B + row * (AS * 2) + (kk * 16 + a_k) * 2;
                ldsm_x4(ah[mt], ad);
                ldsm_x4(al[mt], ad + (A_LO_B - A_HI_B));
            }
#pragma unroll
            for (int g = 0; g < NG; g++) {
                int nrow = wn * (BN / 2) + g * 16 + b_n;
                uint32_t bd = sb + B_HI_B + nrow * (AS * 2) + (kk * 16 + b_k) * 2;
                uint32_t bh[4], bl[4];
                ldsm_x4(bh, bd);                       // non-trans (fix)
                ldsm_x4(bl, bd + (B_LO_B - B_HI_B));   // non-trans (fix)
#pragma unroll
                for (int mt = 0; mt < 2; mt++) {
#pragma unroll
                    for (int j = 0; j < 2; j++) {
                        float* c = acc[mt][g * 2 + j];
                        mma16816(c, ah[mt], bh[2 * j], bh[2 * j + 1]);
                        mma16816(c, ah[mt], bl[2 * j], bl[2 * j + 1]);
                        mma16816(c, al[mt], bh[2 * j], bh[2 * j + 1]);
                    }
                }
            }
        }
        __syncthreads();
    }

    // --- epilogue: dinv row scale, direct gmem store (32B-contiguous groups) ---
    const int gid = lane >> 2, tig = lane & 3;
#pragma unroll
    for (int mt = 0; mt < 2; mt++) {
        int r0 = rowBase + wm * 32 + mt * 16 + gid;
        int r1 = r0 + 8;
        float dv0 = (r0 < NN) ? g_dinv[r0] : 0.f;
        float dv1 = (r1 < NN) ? g_dinv[r1] : 0.f;
#pragma unroll
        for (int nt = 0; nt < NT; nt++) {
            int col = wn * (BN / 2) + nt * 8 + tig * 2;
            if (r0 < NN)
                *(float2*)&hs[r0 * BN + col] =
                    make_float2(acc[mt][nt][0] * dv0, acc[mt][nt][1] * dv0);
            if (r1 < NN)
                *(float2*)&hs[r1 * BN + col] =
                    make_float2(acc[mt][nt][2] * dv1, acc[mt][nt][3] * dv1);
        }
    }
}

// ---------------- CSR gather-aggregate + fused epilogue ----------------

__launch_bounds__(256)
__global__ void agg1_kernel(const float* __restrict__ bias) {
    int w = threadIdx.x >> 5, lane = threadIdx.x & 31;
    int r = blockIdx.x * 8 + w;
    if (r >= NN) return;
    const float4* hs4 = (const float4*)g_hs1;
    float4 a0 = hs4[r * 32 + lane];
    float4 a1 = make_float4(0.f, 0.f, 0.f, 0.f);
    int beg = g_off[r], end = beg + g_deg[r];
    int i = beg;
    for (; i + 1 < end; i += 2) {
        int s0 = __ldg(&g_csr[i]);
        int s1 = __ldg(&g_csr[i + 1]);
        float4 v0 = hs4[s0 * 32 + lane];
        float4 v1 = hs4[s1 * 32 + lane];
        a0.x += v0.x; a0.y += v0.y; a0.z += v0.z; a0.w += v0.w;
        a1.x += v1.x; a1.y += v1.y; a1.z += v1.z; a1.w += v1.w;
    }
    if (i < end) {
        int s0 = __ldg(&g_csr[i]);
        float4 v0 = hs4[s0 * 32 + lane];
        a0.x += v0.x; a0.y += v0.y; a0.z += v0.z; a0.w += v0.w;
    }
    a0.x += a1.x; a0.y += a1.y; a0.z += a1.z; a0.w += a1.w;
    float dv = g_dinv[r];
    float4 bb = ((const float4*)bias)[lane];
    float4 o;
    o.x = fmaxf(a0.x * dv + bb.x, 0.f);
    o.y = fmaxf(a0.y * dv + bb.y, 0.f);
    o.z = fmaxf(a0.z * dv + bb.z, 0.f);
    o.w = fmaxf(a0.w * dv + bb.w, 0.f);
    ((float4*)g_h1)[r * 32 + lane] = o;
}

__launch_bounds__(256)
__global__ void agg2_kernel(const float* __restrict__ bias,
                            float* __restrict__ out) {
    int w = threadIdx.x >> 5, lane = threadIdx.x & 31;
    int r = blockIdx.x * 16 + w * 2 + (lane >> 4);
    int l16 = lane & 15;
    if (r >= NN) return;
    const float4* hs4 = (const float4*)g_hs2;
    float4 a0 = hs4[r * 16 + l16];
    float4 a1 = make_float4(0.f, 0.f, 0.f, 0.f);
    int beg = g_off[r], end = beg + g_deg[r];
    int i = beg;
    for (; i + 1 < end; i += 2) {
        int s0 = __ldg(&g_csr[i]);
        int s1 = __ldg(&g_csr[i + 1]);
        float4 v0 = hs4[s0 * 16 + l16];
        float4 v1 = hs4[s1 * 16 + l16];
        a0.x += v0.x; a0.y += v0.y; a0.z += v0.z; a0.w += v0.w;
        a1.x += v1.x; a1.y += v1.y; a1.z += v1.z; a1.w += v1.w;
    }
    if (i < end) {
        int s0 = __ldg(&g_csr[i]);
        float4 v0 = hs4[s0 * 16 + l16];
        a0.x += v0.x; a0.y += v0.y; a0.z += v0.z; a0.w += v0.w;
    }
    a0.x += a1.x; a0.y += a1.y; a0.z += a1.z; a0.w += a1.w;
    float dv = g_dinv[r];
    float4 bb = ((const float4*)bias)[l16];
    float4 o;
    o.x = fmaxf(a0.x * dv + bb.x, 0.f);
    o.y = fmaxf(a0.y * dv + bb.y, 0.f);
    o.z = fmaxf(a0.z * dv + bb.z, 0.f);
    o.w = fmaxf(a0.w * dv + bb.w, 0.f);
    ((float4*)out)[r * 16 + l16] = o;
}

extern "C" void kernel_launch(void* const* d_in, const int* in_sizes, int n_in,
                              void* d_out, int out_size) {
    const float* x  = (const float*)d_in[0];
    const int*   ei = (const int*)d_in[1];
    const float* W1 = (const float*)d_in[2];
    const float* b1 = (const float*)d_in[3];
    const float* W2 = (const float*)d_in[4];
    const float* b2 = (const float*)d_in[5];
    float* out = (float*)d_out;

    float *p_hs1, *p_h1, *p_hs2;
    __nv_bfloat16 *p_w1h, *p_w1l, *p_w2h, *p_w2l;
    cudaGetSymbolAddress((void**)&p_hs1, g_hs1);
    cudaGetSymbolAddress((void**)&p_h1,  g_h1);
    cudaGetSymbolAddress((void**)&p_hs2, g_hs2);
    cudaGetSymbolAddress((void**)&p_w1h, g_w1t_hi);
    cudaGetSymbolAddress((void**)&p_w1l, g_w1t_lo);
    cudaGetSymbolAddress((void**)&p_w2h, g_w2t_hi);
    cudaGetSymbolAddress((void**)&p_w2l, g_w2t_lo);

    // dynamic smem: 2*(BM+BN)*(BK+8)*2 bytes
    const int SMEM1 = 2 * (128 + 128) * 72 * 2;   // 73728
    const int SMEM2 = 2 * (128 + 64) * 72 * 2;    // 55296
    cudaFuncSetAttribute(gemm_mma_kernel<D0, D1>,
                         cudaFuncAttributeMaxDynamicSharedMemorySize, SMEM1);
    cudaFuncSetAttribute(gemm_mma_kernel<D1, D2>,
                         cudaFuncAttributeMaxDynamicSharedMemorySize, SMEM2);

    // degree + dinv + weight prep
    zero_deg_kernel<<<(NN + 255) / 256, 256>>>();
    count_deg_kernel<<<(NE + 255) / 256, 256>>>(ei);
    dinv_kernel<<<(NN + 255) / 256, 256>>>();
    conv_w_kernel<D0, D1><<<(D0 * D1 + 255) / 256, 256>>>(W1, p_w1h, p_w1l);
    conv_w_kernel<D1, D2><<<(D1 * D2 + 255) / 256, 256>>>(W2, p_w2h, p_w2l);

    // CSR build
    scan_partial_kernel<<<SC_NB, SC_BLK>>>();
    scan_blk_kernel<<<1, 256>>>();
    scan_add_zero_kernel<<<SC_NB, SC_BLK>>>();
    csr_fill_kernel<<<(NE + 255) / 256, 256>>>(ei);

    // layer 1
    gemm_mma_kernel<D0, D1><<<(NN + 127) / 128, 256, SMEM1>>>(x, p_w1h, p_w1l, p_hs1);
    agg1_kernel<<<(NN + 7) / 8, 256>>>(b1);

    // layer 2
    gemm_mma_kernel<D1, D2><<<(NN + 127) / 128, 256, SMEM2>>>(p_h1, p_w2h, p_w2l, p_hs2);
    agg2_kernel<<<(NN + 15) / 16, 256>>>(b2, out);
}